// round 11
// baseline (speedup 1.0000x reference)
#include <cuda_runtime.h>

#define NNODES 4096
#define MASK_WORDS 128   // 4096/32
#define NGRAPH 64
#define MAXNBR 320       // binomial(4096,0.02): mean 82, sigma 9 (clamped defensively)

// ---------------- scratch (no allocations allowed) ----------------
__device__ unsigned g_mask[NNODES * MASK_WORDS];  // 2 MB bitmask of adj>0
__device__ float    g_f[NNODES * 64];             // per-layer head features [N][64]
__device__ float    g_s[4 * NNODES];              // s1h0, s1h1, s2h0, s2h1
__device__ float    g_h[NNODES * 192];            // concat(x1,x2,x3)

// ---------------- K1: f = X @ Wcat + bcat, fused s1/s2 epilogue ----------------
// 16-row x 64-col tiles, 128 threads, register-prefetch pipeline. grid = 256.
// W layout: [2][K][32] (head, k, feat). Output g_f[row][head*32+feat].
__global__ void __launch_bounds__(128) gemm_f(
        const float* __restrict__ Xext, int use_h, int hcol,
        int ldx, int K,
        const float* __restrict__ W, const float* __restrict__ b,
        const float* __restrict__ a1w, const float* __restrict__ a1b,
        const float* __restrict__ a2w, const float* __restrict__ a2b) {
    __shared__ float As[16][33];
    __shared__ float Bs[32][64];
    const float* X = use_h ? (g_h + hcol) : Xext;
    int t = threadIdx.x;             // 128 threads
    int row0 = blockIdx.x * 16;
    int tx = t & 15, ty = t >> 4;    // tx: 16 col-groups of 4, ty: 8 row-pairs

    float acc[2][4] = {};
    float aR[4];
    float4 bR[4];

    const int KT = K >> 5;

    #pragma unroll
    for (int i = 0; i < 4; i++) {
        int idx = t + i * 128;
        aR[i] = X[(size_t)(row0 + (idx >> 5)) * ldx + (idx & 31)];
        int kk = idx >> 4, f4g = idx & 15;
        int head = f4g >> 3, f4 = f4g & 7;
        bR[i] = *reinterpret_cast<const float4*>(&W[(size_t)(head * K + kk) * 32 + f4 * 4]);
    }

    for (int kt = 0; kt < KT; kt++) {
        __syncthreads();
        #pragma unroll
        for (int i = 0; i < 4; i++) {
            int idx = t + i * 128;
            As[idx >> 5][idx & 31] = aR[i];
            int kk = idx >> 4, f4g = idx & 15;
            reinterpret_cast<float4*>(&Bs[kk][0])[f4g] = bR[i];
        }
        __syncthreads();
        if (kt + 1 < KT) {
            int k0 = (kt + 1) << 5;
            #pragma unroll
            for (int i = 0; i < 4; i++) {
                int idx = t + i * 128;
                aR[i] = X[(size_t)(row0 + (idx >> 5)) * ldx + (k0 + (idx & 31))];
                int kk = idx >> 4, f4g = idx & 15;
                int head = f4g >> 3, f4 = f4g & 7;
                bR[i] = *reinterpret_cast<const float4*>(&W[(size_t)(head * K + k0 + kk) * 32 + f4 * 4]);
            }
        }
        #pragma unroll
        for (int kk = 0; kk < 32; kk++) {
            float a0 = As[ty * 2 + 0][kk];
            float a1 = As[ty * 2 + 1][kk];
            float4 bv = reinterpret_cast<const float4*>(&Bs[kk][0])[tx];
            acc[0][0] += a0 * bv.x; acc[0][1] += a0 * bv.y;
            acc[0][2] += a0 * bv.z; acc[0][3] += a0 * bv.w;
            acc[1][0] += a1 * bv.x; acc[1][1] += a1 * bv.y;
            acc[1][2] += a1 * bv.z; acc[1][3] += a1 * bv.w;
        }
    }

    float p1[2] = {0.f, 0.f}, p2[2] = {0.f, 0.f};
    #pragma unroll
    for (int rr = 0; rr < 2; rr++) {
        #pragma unroll
        for (int j = 0; j < 4; j++) {
            int n = (tx << 2) + j;
            float v = acc[rr][j] + b[n];
            g_f[(size_t)(row0 + ty * 2 + rr) * 64 + n] = v;
            p1[rr] += v * a1w[n];
            p2[rr] += v * a2w[n];
        }
    }
    #pragma unroll
    for (int o = 1; o < 8; o <<= 1) {
        p1[0] += __shfl_xor_sync(0xffffffffu, p1[0], o);
        p1[1] += __shfl_xor_sync(0xffffffffu, p1[1], o);
        p2[0] += __shfl_xor_sync(0xffffffffu, p2[0], o);
        p2[1] += __shfl_xor_sync(0xffffffffu, p2[1], o);
    }
    if ((tx & 7) == 0) {
        int head = tx >> 3;
        int r0 = row0 + ty * 2;
        g_s[head * NNODES + r0]           = p1[0] + a1b[head];
        g_s[head * NNODES + r0 + 1]       = p1[1] + a1b[head];
        g_s[(2 + head) * NNODES + r0]     = p2[0] + a2b[head];
        g_s[(2 + head) * NNODES + r0 + 1] = p2[1] + a2b[head];
    }
}

// ---------------- attention body, 2 warps per row ----------------
// CTA = 256 thr = 8 warps = 4 rows. r = warp>>1 (row slot), half = warp&1.
// Phases B/C/D split the neighbor range between the warp pair; per-row merges
// via s_red / s_part + __syncthreads (uniform across CTA).
struct AttnSmem {
    unsigned short idx[4][MAXNBR];
    float e0[4][MAXNBR];
    float e1[4][MAXNBR];
    float red[4][2][4];     // [row][half][mx0,mx1,sum0,sum1]
    float part[4][64];
};

__device__ __forceinline__ void attn_body2(AttnSmem* S, int r, int half,
                                           int lane, int row, int cnt, int hoff) {
    // Phase B: logits (leaky relu) + local max over this half's range
    float s1_0 = g_s[row], s1_1 = g_s[NNODES + row];
    float mx0 = -1e30f, mx1 = -1e30f;
    for (int t = half * 32 + lane; t < cnt; t += 64) {
        int j = S->idx[r][t];
        float e0 = s1_0 + g_s[2 * NNODES + j];
        float e1 = s1_1 + g_s[3 * NNODES + j];
        e0 = e0 > 0.f ? e0 : 0.01f * e0;
        e1 = e1 > 0.f ? e1 : 0.01f * e1;
        S->e0[r][t] = e0; S->e1[r][t] = e1;
        mx0 = fmaxf(mx0, e0); mx1 = fmaxf(mx1, e1);
    }
    #pragma unroll
    for (int o = 16; o; o >>= 1) {
        mx0 = fmaxf(mx0, __shfl_xor_sync(0xffffffffu, mx0, o));
        mx1 = fmaxf(mx1, __shfl_xor_sync(0xffffffffu, mx1, o));
    }
    if (lane == 0) { S->red[r][half][0] = mx0; S->red[r][half][1] = mx1; }
    __syncthreads();
    mx0 = fmaxf(S->red[r][0][0], S->red[r][1][0]);
    mx1 = fmaxf(S->red[r][0][1], S->red[r][1][1]);

    // Phase C: exp + local sum (same half range; same-thread t mapping, no hazard)
    float sum0 = 0.f, sum1 = 0.f;
    for (int t = half * 32 + lane; t < cnt; t += 64) {
        float w0 = __expf(S->e0[r][t] - mx0);
        float w1 = __expf(S->e1[r][t] - mx1);
        S->e0[r][t] = w0; S->e1[r][t] = w1;
        sum0 += w0; sum1 += w1;
    }
    #pragma unroll
    for (int o = 16; o; o >>= 1) {
        sum0 += __shfl_xor_sync(0xffffffffu, sum0, o);
        sum1 += __shfl_xor_sync(0xffffffffu, sum1, o);
    }
    if (lane == 0) { S->red[r][half][2] = sum0; S->red[r][half][3] = sum1; }
    __syncthreads();
    float inv0 = 1.f / (S->red[r][0][2] + S->red[r][1][2]);
    float inv1 = 1.f / (S->red[r][0][3] + S->red[r][1][3]);

    // Phase D: this half accumulates alternating neighbors; merge via s_part
    float acc0 = 0.f, acc1 = 0.f;
    #pragma unroll 4
    for (int t = half; t < cnt; t += 2) {
        float w0 = S->e0[r][t];
        float w1 = S->e1[r][t];
        const float* fj = &g_f[(size_t)S->idx[r][t] * 64];
        acc0 += w0 * fj[lane];
        acc1 += w1 * fj[32 + lane];
    }
    if (half) { S->part[r][lane] = acc0; S->part[r][32 + lane] = acc1; }
    __syncthreads();
    if (!half) {
        acc0 += S->part[r][lane];
        acc1 += S->part[r][32 + lane];
        float* hr = &g_h[(size_t)row * 192 + hoff];
        float o0 = acc0 * inv0, o1 = acc1 * inv1;
        hr[lane]      = o0 > 0.f ? o0 : 0.f;
        hr[32 + lane] = o1 > 0.f ? o1 : 0.f;
    }
}

// gather indices from 128 mask words held in smem (both warps do identical work;
// identical duplicate s_idx writes are benign)
__device__ __forceinline__ int gather_from_words(AttnSmem* S, int r, int lane,
                                                 const unsigned* words) {
    unsigned m[4];
    int c = 0;
    #pragma unroll
    for (int i = 0; i < 4; i++) { m[i] = words[lane * 4 + i]; c += __popc(m[i]); }
    int inc = c;
    #pragma unroll
    for (int o = 1; o < 32; o <<= 1) {
        int n = __shfl_up_sync(0xffffffffu, inc, o);
        if (lane >= o) inc += n;
    }
    int cnt = __shfl_sync(0xffffffffu, inc, 31);
    int pos = inc - c;
    #pragma unroll
    for (int i = 0; i < 4; i++) {
        unsigned mm = m[i];
        int base = (lane * 4 + i) * 32;
        while (mm) {
            int bp = __ffs(mm) - 1; mm &= mm - 1;
            if (pos < MAXNBR) S->idx[r][pos] = (unsigned short)(base + bp);
            pos++;
        }
    }
    return cnt > MAXNBR ? MAXNBR : cnt;
}

// ---------------- K2a: layer-1 attention fused with mask build (reads adj) ----------------
__global__ void __launch_bounds__(256) attn_build(const float* __restrict__ adj) {
    __shared__ AttnSmem S;
    __shared__ unsigned s_words[4][MASK_WORDS];   // 2 KB

    int wp = threadIdx.x >> 5, lane = threadIdx.x & 31;
    int r = wp >> 1, half = wp & 1;
    int row = blockIdx.x * 4 + r;

    // Phase A0: warp pair splits the adj row read (8 KB each)
    const float4* arow = reinterpret_cast<const float4*>(adj + (size_t)row * NNODES);
    #pragma unroll 4
    for (int g = half * 16; g < half * 16 + 16; g++) {
        float4 v = arow[g * 32 + lane];
        unsigned b0 = __ballot_sync(0xffffffffu, v.x > 0.0f);
        unsigned b1 = __ballot_sync(0xffffffffu, v.y > 0.0f);
        unsigned b2 = __ballot_sync(0xffffffffu, v.z > 0.0f);
        unsigned b3 = __ballot_sync(0xffffffffu, v.w > 0.0f);
        if (lane < 4) {
            int sh = lane * 8;
            unsigned n0 = (b0 >> sh) & 0xffu;
            unsigned n1 = (b1 >> sh) & 0xffu;
            unsigned n2 = (b2 >> sh) & 0xffu;
            unsigned n3 = (b3 >> sh) & 0xffu;
            unsigned w = 0;
            #pragma unroll
            for (int i = 0; i < 8; i++) {
                w |= ((n0 >> i) & 1u) << (i * 4 + 0);
                w |= ((n1 >> i) & 1u) << (i * 4 + 1);
                w |= ((n2 >> i) & 1u) << (i * 4 + 2);
                w |= ((n3 >> i) & 1u) << (i * 4 + 3);
            }
            s_words[r][g * 4 + lane] = w;
        }
    }
    __syncthreads();

    // persist mask for layers 2/3 (split between the pair)
    #pragma unroll
    for (int i = 0; i < 2; i++) {
        int w = half * 64 + lane * 2 + i;
        g_mask[row * MASK_WORDS + w] = s_words[r][w];
    }

    int cnt = gather_from_words(&S, r, lane, s_words[r]);
    __syncwarp();

    attn_body2(&S, r, half, lane, row, cnt, 0);
}

// ---------------- K2b: layers 2/3 attention (reads 2MB L2-resident mask) ----------------
__global__ void __launch_bounds__(256) attn_kernel(int hoff) {
    __shared__ AttnSmem S;

    int wp = threadIdx.x >> 5, lane = threadIdx.x & 31;
    int r = wp >> 1, half = wp & 1;
    int row = blockIdx.x * 4 + r;

    int cnt = gather_from_words(&S, r, lane, &g_mask[row * MASK_WORDS]);
    __syncwarp();

    attn_body2(&S, r, half, lane, row, cnt, hoff);
}

// ---------------- K3: segment-mean pool + classifier + softmax ----------------
__global__ void final_kernel(const int* __restrict__ batch,
                             const float* __restrict__ Wf,
                             const float* __restrict__ bf,
                             float* __restrict__ out) {
    __shared__ float s_pool[192];
    __shared__ float s_log[10];
    int g = blockIdx.x;
    int tid = threadIdx.x;  // 192

    int lo = 0, hi = NNODES;
    while (lo < hi) { int mid = (lo + hi) >> 1; if (batch[mid] < g) lo = mid + 1; else hi = mid; }
    int start = lo;
    lo = start; hi = NNODES;
    while (lo < hi) { int mid = (lo + hi) >> 1; if (batch[mid] < g + 1) lo = mid + 1; else hi = mid; }
    int end = lo;
    int cnt = end - start;

    float sum = 0.f;
    for (int r = start; r < end; r++) sum += g_h[(size_t)r * 192 + tid];
    s_pool[tid] = sum / (float)(cnt > 0 ? cnt : 1);
    __syncthreads();

    if (tid < 10) {
        float l = bf[tid];
        for (int c = 0; c < 192; c++) l += s_pool[c] * Wf[c * 10 + tid];
        s_log[tid] = l;
    }
    __syncthreads();
    if (tid == 0) {
        float m = -1e30f;
        for (int o = 0; o < 10; o++) m = fmaxf(m, s_log[o]);
        float e[10], s = 0.f;
        for (int o = 0; o < 10; o++) { e[o] = __expf(s_log[o] - m); s += e[o]; }
        float inv = 1.f / s;
        for (int o = 0; o < 10; o++) out[g * 10 + o] = e[o] * inv;
    }
}

// ---------------- launch ----------------
extern "C" void kernel_launch(void* const* d_in, const int* in_sizes, int n_in,
                              void* d_out, int out_size) {
    const float* x   = (const float*)d_in[0];
    const float* adj = (const float*)d_in[1];
    const int* batch = (const int*)d_in[2];
    const float* W[3]   = {(const float*)d_in[3],  (const float*)d_in[9],  (const float*)d_in[15]};
    const float* b[3]   = {(const float*)d_in[4],  (const float*)d_in[10], (const float*)d_in[16]};
    const float* a1w[3] = {(const float*)d_in[5],  (const float*)d_in[11], (const float*)d_in[17]};
    const float* a1b[3] = {(const float*)d_in[6],  (const float*)d_in[12], (const float*)d_in[18]};
    const float* a2w[3] = {(const float*)d_in[7],  (const float*)d_in[13], (const float*)d_in[19]};
    const float* a2b[3] = {(const float*)d_in[8],  (const float*)d_in[14], (const float*)d_in[20]};
    const float* Wf = (const float*)d_in[21];
    const float* bf = (const float*)d_in[22];
    float* out = (float*)d_out;

    for (int L = 0; L < 3; L++) {
        int K    = (L == 0) ? 512 : 64;
        int useh = (L == 0) ? 0 : 1;
        int hcol = (L == 0) ? 0 : (L - 1) * 64;
        int ldx  = (L == 0) ? 512 : 192;
        gemm_f<<<NNODES / 16, 128>>>(x, useh, hcol, ldx, K, W[L], b[L],
                                     a1w[L], a1b[L], a2w[L], a2b[L]);
        if (L == 0) attn_build<<<NNODES / 4, 256>>>(adj);
        else        attn_kernel<<<NNODES / 4, 256>>>(L * 64);
    }

    final_kernel<<<NGRAPH, 192>>>(batch, Wf, bf, out);
}

// round 13
// speedup vs baseline: 1.0663x; 1.0663x over previous
#include <cuda_runtime.h>

#define NNODES 4096
#define MASK_WORDS 128   // 4096/32
#define NGRAPH 64
#define MAXNBR 320       // binomial(4096,0.02): mean 82, sigma 9 (clamped defensively)

// ---------------- scratch (no allocations allowed) ----------------
__device__ float          g_f[NNODES * 64];       // per-layer head features [N][64]
__device__ float          g_s1[2 * NNODES];       // s1: [head][row] planar
__device__ float          g_s2[2 * NNODES];       // s2: packed pairs [row]{h0,h1}
__device__ unsigned short g_nbr[NNODES * MAXNBR]; // CSR neighbor lists (built layer 1)
__device__ int            g_cnt[NNODES];          // CSR counts
__device__ float          g_h[NNODES * 192];      // concat(x1,x2,x3)

// ---------------- K1: f = X @ Wcat + bcat, fused s1/s2 epilogue ----------------
// 16-row x 64-col tiles, 128 threads, register-prefetch pipeline. grid = 256.
// W layout: [2][K][32] (head, k, feat). Output g_f[row][head*32+feat].
__global__ void __launch_bounds__(128) gemm_f(
        const float* __restrict__ Xext, int use_h, int hcol,
        int ldx, int K,
        const float* __restrict__ W, const float* __restrict__ b,
        const float* __restrict__ a1w, const float* __restrict__ a1b,
        const float* __restrict__ a2w, const float* __restrict__ a2b) {
    __shared__ float As[16][33];
    __shared__ float Bs[32][64];
    const float* X = use_h ? (g_h + hcol) : Xext;
    int t = threadIdx.x;             // 128 threads
    int row0 = blockIdx.x * 16;
    int tx = t & 15, ty = t >> 4;    // tx: 16 col-groups of 4, ty: 8 row-pairs

    float acc[2][4] = {};
    float aR[4];
    float4 bR[4];

    const int KT = K >> 5;

    #pragma unroll
    for (int i = 0; i < 4; i++) {
        int idx = t + i * 128;
        aR[i] = X[(size_t)(row0 + (idx >> 5)) * ldx + (idx & 31)];
        int kk = idx >> 4, f4g = idx & 15;
        int head = f4g >> 3, f4 = f4g & 7;
        bR[i] = *reinterpret_cast<const float4*>(&W[(size_t)(head * K + kk) * 32 + f4 * 4]);
    }

    for (int kt = 0; kt < KT; kt++) {
        __syncthreads();
        #pragma unroll
        for (int i = 0; i < 4; i++) {
            int idx = t + i * 128;
            As[idx >> 5][idx & 31] = aR[i];
            int kk = idx >> 4, f4g = idx & 15;
            reinterpret_cast<float4*>(&Bs[kk][0])[f4g] = bR[i];
        }
        __syncthreads();
        if (kt + 1 < KT) {
            int k0 = (kt + 1) << 5;
            #pragma unroll
            for (int i = 0; i < 4; i++) {
                int idx = t + i * 128;
                aR[i] = X[(size_t)(row0 + (idx >> 5)) * ldx + (k0 + (idx & 31))];
                int kk = idx >> 4, f4g = idx & 15;
                int head = f4g >> 3, f4 = f4g & 7;
                bR[i] = *reinterpret_cast<const float4*>(&W[(size_t)(head * K + k0 + kk) * 32 + f4 * 4]);
            }
        }
        #pragma unroll
        for (int kk = 0; kk < 32; kk++) {
            float a0 = As[ty * 2 + 0][kk];
            float a1 = As[ty * 2 + 1][kk];
            float4 bv = reinterpret_cast<const float4*>(&Bs[kk][0])[tx];
            acc[0][0] += a0 * bv.x; acc[0][1] += a0 * bv.y;
            acc[0][2] += a0 * bv.z; acc[0][3] += a0 * bv.w;
            acc[1][0] += a1 * bv.x; acc[1][1] += a1 * bv.y;
            acc[1][2] += a1 * bv.z; acc[1][3] += a1 * bv.w;
        }
    }

    float p1[2] = {0.f, 0.f}, p2[2] = {0.f, 0.f};
    #pragma unroll
    for (int rr = 0; rr < 2; rr++) {
        #pragma unroll
        for (int j = 0; j < 4; j++) {
            int n = (tx << 2) + j;
            float v = acc[rr][j] + b[n];
            g_f[(size_t)(row0 + ty * 2 + rr) * 64 + n] = v;
            p1[rr] += v * a1w[n];
            p2[rr] += v * a2w[n];
        }
    }
    #pragma unroll
    for (int o = 1; o < 8; o <<= 1) {
        p1[0] += __shfl_xor_sync(0xffffffffu, p1[0], o);
        p1[1] += __shfl_xor_sync(0xffffffffu, p1[1], o);
        p2[0] += __shfl_xor_sync(0xffffffffu, p2[0], o);
        p2[1] += __shfl_xor_sync(0xffffffffu, p2[1], o);
    }
    if ((tx & 7) == 0) {
        int head = tx >> 3;
        int r0 = row0 + ty * 2;
        g_s1[head * NNODES + r0]     = p1[0] + a1b[head];
        g_s1[head * NNODES + r0 + 1] = p1[1] + a1b[head];
        g_s2[2 * r0 + head]          = p2[0] + a2b[head];
        g_s2[2 * (r0 + 1) + head]    = p2[1] + a2b[head];
    }
}

// ---------------- attention body: 1 row, 64 threads (2 warps) ----------------
// Phases split between the warp pair; merges via tiny smem + 2-warp barriers.
__device__ __forceinline__ void attn_body(const unsigned short* s_idx, float2* s_e,
                                          float (*s_red)[4], float2* s_part,
                                          int tid, int wp, int lane,
                                          int row, int cnt, int hoff) {
    // Phase B: logits (leaky relu) + max, split range t = tid stride 64
    float s1_0 = g_s1[row], s1_1 = g_s1[NNODES + row];
    float mx0 = -1e30f, mx1 = -1e30f;
    for (int t = tid; t < cnt; t += 64) {
        int j = s_idx[t];
        float2 s2 = *reinterpret_cast<const float2*>(&g_s2[2 * j]);
        float e0 = s1_0 + s2.x;
        float e1 = s1_1 + s2.y;
        e0 = e0 > 0.f ? e0 : 0.01f * e0;
        e1 = e1 > 0.f ? e1 : 0.01f * e1;
        s_e[t] = make_float2(e0, e1);
        mx0 = fmaxf(mx0, e0); mx1 = fmaxf(mx1, e1);
    }
    #pragma unroll
    for (int o = 16; o; o >>= 1) {
        mx0 = fmaxf(mx0, __shfl_xor_sync(0xffffffffu, mx0, o));
        mx1 = fmaxf(mx1, __shfl_xor_sync(0xffffffffu, mx1, o));
    }
    if (lane == 0) { s_red[wp][0] = mx0; s_red[wp][1] = mx1; }
    __syncthreads();
    mx0 = fmaxf(s_red[0][0], s_red[1][0]);
    mx1 = fmaxf(s_red[0][1], s_red[1][1]);

    // Phase C: exp + sum (same t mapping as B: no cross-thread smem hazard)
    float sum0 = 0.f, sum1 = 0.f;
    for (int t = tid; t < cnt; t += 64) {
        float2 e = s_e[t];
        float w0 = __expf(e.x - mx0);
        float w1 = __expf(e.y - mx1);
        s_e[t] = make_float2(w0, w1);
        sum0 += w0; sum1 += w1;
    }
    #pragma unroll
    for (int o = 16; o; o >>= 1) {
        sum0 += __shfl_xor_sync(0xffffffffu, sum0, o);
        sum1 += __shfl_xor_sync(0xffffffffu, sum1, o);
    }
    if (lane == 0) { s_red[wp][2] = sum0; s_red[wp][3] = sum1; }
    __syncthreads();
    float inv0 = 1.f / (s_red[0][2] + s_red[1][2]);
    float inv1 = 1.f / (s_red[0][3] + s_red[1][3]);

    // Phase D: lane k owns features {2k, 2k+1} (same head: lane<16 -> h0).
    // Warp wp takes t = wp, wp+2, ... ; merge via s_part.
    float2 acc = make_float2(0.f, 0.f);
    bool h0 = lane < 16;
    #pragma unroll 4
    for (int t = wp; t < cnt; t += 2) {
        float2 e = s_e[t];
        float w = h0 ? e.x : e.y;
        float2 fj = *reinterpret_cast<const float2*>(&g_f[(size_t)s_idx[t] * 64 + 2 * lane]);
        acc.x += w * fj.x;
        acc.y += w * fj.y;
    }
    if (wp) s_part[lane] = acc;
    __syncthreads();
    if (!wp) {
        float2 p = s_part[lane];
        float inv = h0 ? inv0 : inv1;
        float o0 = (acc.x + p.x) * inv;
        float o1 = (acc.y + p.y) * inv;
        *reinterpret_cast<float2*>(&g_h[(size_t)row * 192 + hoff + 2 * lane]) =
            make_float2(o0 > 0.f ? o0 : 0.f, o1 > 0.f ? o1 : 0.f);
    }
}

// ---------------- K2a: layer-1 attention, builds CSR from adj (DRAM read) ----------------
__global__ void __launch_bounds__(64, 24) attn_build(const float* __restrict__ adj) {
    __shared__ unsigned s_words[MASK_WORDS];     // 512 B
    __shared__ unsigned short s_idx[MAXNBR];     // 640 B
    __shared__ float2 s_e[MAXNBR];               // 2.5 KB
    __shared__ float s_red[2][4];
    __shared__ float2 s_part[32];
    __shared__ int s_cnt;

    int tid = threadIdx.x, wp = tid >> 5, lane = tid & 31;
    int row = blockIdx.x;

    // Phase A0: warp pair splits the 16 KB adj row read
    const float4* arow = reinterpret_cast<const float4*>(adj + (size_t)row * NNODES);
    #pragma unroll 4
    for (int g = wp * 16; g < wp * 16 + 16; g++) {
        float4 v = arow[g * 32 + lane];
        unsigned b0 = __ballot_sync(0xffffffffu, v.x > 0.0f);
        unsigned b1 = __ballot_sync(0xffffffffu, v.y > 0.0f);
        unsigned b2 = __ballot_sync(0xffffffffu, v.z > 0.0f);
        unsigned b3 = __ballot_sync(0xffffffffu, v.w > 0.0f);
        if (lane < 4) {
            int sh = lane * 8;
            unsigned n0 = (b0 >> sh) & 0xffu;
            unsigned n1 = (b1 >> sh) & 0xffu;
            unsigned n2 = (b2 >> sh) & 0xffu;
            unsigned n3 = (b3 >> sh) & 0xffu;
            unsigned w = 0;
            #pragma unroll
            for (int i = 0; i < 8; i++) {
                w |= ((n0 >> i) & 1u) << (i * 4 + 0);
                w |= ((n1 >> i) & 1u) << (i * 4 + 1);
                w |= ((n2 >> i) & 1u) << (i * 4 + 2);
                w |= ((n3 >> i) & 1u) << (i * 4 + 3);
            }
            s_words[g * 4 + lane] = w;
        }
    }
    __syncthreads();

    // Phase A1: warp 0 extracts indices (scan over 128 words)
    if (wp == 0) {
        unsigned m[4];
        int c = 0;
        #pragma unroll
        for (int i = 0; i < 4; i++) { m[i] = s_words[lane * 4 + i]; c += __popc(m[i]); }
        int inc = c;
        #pragma unroll
        for (int o = 1; o < 32; o <<= 1) {
            int n = __shfl_up_sync(0xffffffffu, inc, o);
            if (lane >= o) inc += n;
        }
        int cw = __shfl_sync(0xffffffffu, inc, 31);
        int pos = inc - c;
        #pragma unroll
        for (int i = 0; i < 4; i++) {
            unsigned mm = m[i];
            int base = (lane * 4 + i) * 32;
            while (mm) {
                int bp = __ffs(mm) - 1; mm &= mm - 1;
                if (pos < MAXNBR) s_idx[pos] = (unsigned short)(base + bp);
                pos++;
            }
        }
        if (lane == 0) s_cnt = cw > MAXNBR ? MAXNBR : cw;
    }
    __syncthreads();
    int cnt = s_cnt;

    // persist CSR for layers 2/3
    for (int t = tid; t < cnt; t += 64) g_nbr[(size_t)row * MAXNBR + t] = s_idx[t];
    if (tid == 0) g_cnt[row] = cnt;

    attn_body(s_idx, s_e, s_red, s_part, tid, wp, lane, row, cnt, 0);
}

// ---------------- K2b: layers 2/3 attention (reads CSR) ----------------
__global__ void __launch_bounds__(64, 24) attn_kernel(int hoff) {
    __shared__ unsigned short s_idx[MAXNBR];
    __shared__ float2 s_e[MAXNBR];
    __shared__ float s_red[2][4];
    __shared__ float2 s_part[32];

    int tid = threadIdx.x, wp = tid >> 5, lane = tid & 31;
    int row = blockIdx.x;

    int cnt = g_cnt[row];
    for (int t = tid; t < cnt; t += 64) s_idx[t] = g_nbr[(size_t)row * MAXNBR + t];
    __syncthreads();

    attn_body(s_idx, s_e, s_red, s_part, tid, wp, lane, row, cnt, hoff);
}

// ---------------- K3: segment-mean pool + classifier + softmax ----------------
__global__ void final_kernel(const int* __restrict__ batch,
                             const float* __restrict__ Wf,
                             const float* __restrict__ bf,
                             float* __restrict__ out) {
    __shared__ float s_pool[192];
    __shared__ float s_log[10];
    int g = blockIdx.x;
    int tid = threadIdx.x;  // 192

    int lo = 0, hi = NNODES;
    while (lo < hi) { int mid = (lo + hi) >> 1; if (batch[mid] < g) lo = mid + 1; else hi = mid; }
    int start = lo;
    lo = start; hi = NNODES;
    while (lo < hi) { int mid = (lo + hi) >> 1; if (batch[mid] < g + 1) lo = mid + 1; else hi = mid; }
    int end = lo;
    int cnt = end - start;

    float sum = 0.f;
    for (int r = start; r < end; r++) sum += g_h[(size_t)r * 192 + tid];
    s_pool[tid] = sum / (float)(cnt > 0 ? cnt : 1);
    __syncthreads();

    if (tid < 10) {
        float l = bf[tid];
        for (int c = 0; c < 192; c++) l += s_pool[c] * Wf[c * 10 + tid];
        s_log[tid] = l;
    }
    __syncthreads();
    if (tid == 0) {
        float m = -1e30f;
        for (int o = 0; o < 10; o++) m = fmaxf(m, s_log[o]);
        float e[10], s = 0.f;
        for (int o = 0; o < 10; o++) { e[o] = __expf(s_log[o] - m); s += e[o]; }
        float inv = 1.f / s;
        for (int o = 0; o < 10; o++) out[g * 10 + o] = e[o] * inv;
    }
}

// ---------------- launch ----------------
extern "C" void kernel_launch(void* const* d_in, const int* in_sizes, int n_in,
                              void* d_out, int out_size) {
    const float* x   = (const float*)d_in[0];
    const float* adj = (const float*)d_in[1];
    const int* batch = (const int*)d_in[2];
    const float* W[3]   = {(const float*)d_in[3],  (const float*)d_in[9],  (const float*)d_in[15]};
    const float* b[3]   = {(const float*)d_in[4],  (const float*)d_in[10], (const float*)d_in[16]};
    const float* a1w[3] = {(const float*)d_in[5],  (const float*)d_in[11], (const float*)d_in[17]};
    const float* a1b[3] = {(const float*)d_in[6],  (const float*)d_in[12], (const float*)d_in[18]};
    const float* a2w[3] = {(const float*)d_in[7],  (const float*)d_in[13], (const float*)d_in[19]};
    const float* a2b[3] = {(const float*)d_in[8],  (const float*)d_in[14], (const float*)d_in[20]};
    const float* Wf = (const float*)d_in[21];
    const float* bf = (const float*)d_in[22];
    float* out = (float*)d_out;

    for (int L = 0; L < 3; L++) {
        int K    = (L == 0) ? 512 : 64;
        int useh = (L == 0) ? 0 : 1;
        int hcol = (L == 0) ? 0 : (L - 1) * 64;
        int ldx  = (L == 0) ? 512 : 192;
        gemm_f<<<NNODES / 16, 128>>>(x, useh, hcol, ldx, K, W[L], b[L],
                                     a1w[L], a1b[L], a2w[L], a2b[L]);
        if (L == 0) attn_build<<<NNODES, 64>>>(adj);
        else        attn_kernel<<<NNODES, 64>>>(L * 64);
    }

    final_kernel<<<NGRAPH, 192>>>(batch, Wf, bf, out);
}